// round 11
// baseline (speedup 1.0000x reference)
#include <cuda_runtime.h>
#include <cuda_fp16.h>
#include <cstdint>

#define BB 16
#define NN 1024
#define UU 64
#define MAXDEG 128
#define ALPHA 0.2f

// ---------------- scratch (device globals; no allocations) ----------------
__device__ int     g_cnt[NN];
__device__ int     g_nbr[NN * MAXDEG];
__device__ __half2 g_h1h[BB * NN * 64];   // h1 fp16, 128 cols = 64 half2
__device__ __half2 g_h2h[BB * NN * 32];   // h2 fp16, 64 cols = 32 half2
__device__ float   g_h2a[BB * NN * 64];   // X @ W2[:64] partial (fp32)
__device__ float   g_s1s[BB * NN];
__device__ float   g_s1d[BB * NN];
__device__ float   g_z  [BB * NN * UU];
__device__ float   g_rs [BB * NN * UU];   // r * state
__device__ float   g_s2s[BB * NN];
__device__ float   g_s2d[BB * NN];

__device__ __forceinline__ uint32_t smem_u32(const void* p) {
    uint32_t a;
    asm("{ .reg .u64 t; cvta.to.shared.u64 t, %1; cvt.u32.u64 %0, t; }" : "=r"(a) : "l"(p));
    return a;
}
__device__ __forceinline__ void ldm_x4(uint32_t& r0, uint32_t& r1, uint32_t& r2, uint32_t& r3,
                                       uint32_t addr) {
    asm volatile("ldmatrix.sync.aligned.m8n8.x4.shared.b16 {%0,%1,%2,%3}, [%4];"
                 : "=r"(r0), "=r"(r1), "=r"(r2), "=r"(r3) : "r"(addr));
}
__device__ __forceinline__ void ldm_x4t(uint32_t& r0, uint32_t& r1, uint32_t& r2, uint32_t& r3,
                                        uint32_t addr) {
    asm volatile("ldmatrix.sync.aligned.m8n8.x4.trans.shared.b16 {%0,%1,%2,%3}, [%4];"
                 : "=r"(r0), "=r"(r1), "=r"(r2), "=r"(r3) : "r"(addr));
}
__device__ __forceinline__ void mma16816(float* c, uint32_t a0, uint32_t a1, uint32_t a2,
                                         uint32_t a3, uint32_t b0, uint32_t b1) {
    asm volatile(
        "mma.sync.aligned.m16n8k16.row.col.f32.f16.f16.f32 "
        "{%0,%1,%2,%3}, {%4,%5,%6,%7}, {%8,%9}, {%0,%1,%2,%3};"
        : "+f"(c[0]), "+f"(c[1]), "+f"(c[2]), "+f"(c[3])
        : "r"(a0), "r"(a1), "r"(a2), "r"(a3), "r"(b0), "r"(b1));
}
__device__ __forceinline__ void cvt_store8(__half* dst, float4 f0, float4 f1) {
    __half2 h0 = __floats2half2_rn(f0.x, f0.y);
    __half2 h1 = __floats2half2_rn(f0.z, f0.w);
    __half2 h2 = __floats2half2_rn(f1.x, f1.y);
    __half2 h3 = __floats2half2_rn(f1.z, f1.w);
    uint4 pk;
    pk.x = *reinterpret_cast<unsigned*>(&h0);
    pk.y = *reinterpret_cast<unsigned*>(&h1);
    pk.z = *reinterpret_cast<unsigned*>(&h2);
    pk.w = *reinterpret_cast<unsigned*>(&h3);
    *reinterpret_cast<uint4*>(dst) = pk;
}

// ---------------- K0: neighbor-list build via warp ballots ----------------
__global__ __launch_bounds__(256) void k_build(const float* __restrict__ adj) {
    int i = blockIdx.x, t = threadIdx.x, lane = t & 31, w = t >> 5;
    __shared__ int wtot[8];

    float4 v = *reinterpret_cast<const float4*>(adj + (size_t)i * NN + t * 4);
    unsigned f0 = v.x > 0.f, f1 = v.y > 0.f, f2 = v.z > 0.f, f3 = v.w > 0.f;
    unsigned m0 = __ballot_sync(~0u, f0), m1 = __ballot_sync(~0u, f1);
    unsigned m2 = __ballot_sync(~0u, f2), m3 = __ballot_sync(~0u, f3);
    unsigned lt = (1u << lane) - 1u;
    int pre = __popc(m0 & lt) + __popc(m1 & lt) + __popc(m2 & lt) + __popc(m3 & lt);
    if (lane == 0) wtot[w] = __popc(m0) + __popc(m1) + __popc(m2) + __popc(m3);
    __syncthreads();
    int base = 0;
    #pragma unroll
    for (int q = 0; q < 8; q++) base += (q < w) ? wtot[q] : 0;
    int p = base + pre;
    if (f0) { if (p < MAXDEG) g_nbr[i * MAXDEG + p] = t * 4 + 0; p++; }
    if (f1) { if (p < MAXDEG) g_nbr[i * MAXDEG + p] = t * 4 + 1; p++; }
    if (f2) { if (p < MAXDEG) g_nbr[i * MAXDEG + p] = t * 4 + 2; p++; }
    if (f3) { if (p < MAXDEG) g_nbr[i * MAXDEG + p] = t * 4 + 3; p++; }
    if (t == 255) {
        int tot = base + wtot[7];
        g_cnt[i] = tot < MAXDEG ? tot : MAXDEG;
    }
}

// ---------------- K1: fused gemm1 + h2a partial ----------------
// Per block (b, 64-row M-tile):
//   h1 = fp16( [X|state] @ W1[128,128] ), s1s/s1d scores
//   h2a = fp32( X @ W2[0:64,0:64] )       (NO s2 scores here — k_h2b owns them)
__global__ __launch_bounds__(256)
void k_g1(const float* __restrict__ xa, const float* __restrict__ xbs,
          const float* __restrict__ W1, const float* __restrict__ a1,
          const float* __restrict__ W2) {
    constexpr int AP = 136;
    constexpr int BP1 = 136;   // W1 pad
    constexpr int BP2 = 72;    // W2top pad

    extern __shared__ char sm[];
    __half* As  = (__half*)sm;                                  // [64][AP]
    __half* B1s = (__half*)(sm + 64 * AP * 2);                  // [128][BP1]
    __half* B2s = (__half*)(sm + 64 * AP * 2 + 128 * BP1 * 2);  // [64][BP2]
    float*  sA1 = (float*)(sm + 64 * AP * 2 + 128 * BP1 * 2 + 64 * BP2 * 2); // [256]
    float*  sr1 = sA1 + 256;                                    // [256]

    int tid = threadIdx.x, w = tid >> 5, lane = tid & 31;
    int b = blockIdx.y;
    int row0 = blockIdx.x * 64;

    // ---- stage A: 64 rows x [X|state], fp32->fp16 ----
    #pragma unroll
    for (int it = 0; it < 4; it++) {
        int idx = it * 256 + tid;
        int row = idx >> 4;
        int col0 = (idx & 15) * 8;
        const float* src = (col0 < 64)
            ? xa + ((size_t)b * NN + row0 + row) * 64 + col0
            : xbs + ((size_t)b * NN + row0 + row) * 64 + (col0 - 64);
        float4 f0 = *reinterpret_cast<const float4*>(src);
        float4 f1 = *reinterpret_cast<const float4*>(src + 4);
        cvt_store8(As + row * AP + col0, f0, f1);
    }
    // ---- stage B1 = W1: [128][128] ----
    #pragma unroll
    for (int it = 0; it < 8; it++) {
        int idx = it * 256 + tid;
        int k = idx >> 4;
        int n0 = (idx & 15) * 8;
        float4 f0 = *reinterpret_cast<const float4*>(W1 + (size_t)k * 128 + n0);
        float4 f1 = *reinterpret_cast<const float4*>(W1 + (size_t)k * 128 + n0 + 4);
        cvt_store8(B1s + k * BP1 + n0, f0, f1);
    }
    // ---- stage B2 = W2[0:64]: [64][64] ----
    #pragma unroll
    for (int it = 0; it < 2; it++) {
        int idx = it * 256 + tid;
        int k = idx >> 3;
        int n0 = (idx & 7) * 8;
        float4 f0 = *reinterpret_cast<const float4*>(W2 + (size_t)k * 64 + n0);
        float4 f1 = *reinterpret_cast<const float4*>(W2 + (size_t)k * 64 + n0 + 4);
        cvt_store8(B2s + k * BP2 + n0, f0, f1);
    }
    if (tid < 256) sA1[tid] = a1[tid];
    __syncthreads();

    // ---- mainloop ----
    int mrow = (w & 3) * 16, nh = w >> 2;
    float acc1[8][4], acc2[4][4];
    #pragma unroll
    for (int j = 0; j < 8; j++)
        #pragma unroll
        for (int q = 0; q < 4; q++) acc1[j][q] = 0.f;
    #pragma unroll
    for (int j = 0; j < 4; j++)
        #pragma unroll
        for (int q = 0; q < 4; q++) acc2[j][q] = 0.f;

    uint32_t a_base  = smem_u32(As  + (mrow + (lane & 15)) * AP + ((lane >> 4) * 8));
    uint32_t b1_base = smem_u32(B1s + (lane & 15) * BP1 + nh * 64 + ((lane >> 4) * 8));
    uint32_t b2_base = smem_u32(B2s + (lane & 15) * BP2 + nh * 32 + ((lane >> 4) * 8));

    #pragma unroll
    for (int kk = 0; kk < 8; kk++) {
        uint32_t a0, a1r, a2r, a3;
        ldm_x4(a0, a1r, a2r, a3, a_base + kk * 32);
        #pragma unroll
        for (int j = 0; j < 4; j++) {
            uint32_t b0, b1, b2, b3;
            ldm_x4t(b0, b1, b2, b3, b1_base + kk * (16 * BP1 * 2) + j * 32);
            mma16816(acc1[2 * j],     a0, a1r, a2r, a3, b0, b1);
            mma16816(acc1[2 * j + 1], a0, a1r, a2r, a3, b2, b3);
        }
        if (kk < 4) {   // h2a: X part only (A cols 0..63), W2top
            #pragma unroll
            for (int j = 0; j < 2; j++) {
                uint32_t b0, b1, b2, b3;
                ldm_x4t(b0, b1, b2, b3, b2_base + kk * (16 * BP2 * 2) + j * 32);
                mma16816(acc2[2 * j],     a0, a1r, a2r, a3, b0, b1);
                mma16816(acc2[2 * j + 1], a0, a1r, a2r, a3, b2, b3);
            }
        }
    }

    // ---- epilogue ----
    int q = lane & 3, g = lane >> 2;
    int rowA = mrow + g, rowB = rowA + 8;
    size_t sbA = (size_t)b * NN + row0 + rowA;
    size_t sbB = (size_t)b * NN + row0 + rowB;
    __half2* hrA = g_h1h + sbA * 64;
    __half2* hrB = g_h1h + sbB * 64;

    float ps0 = 0.f, pd0 = 0.f, ps1 = 0.f, pd1 = 0.f;
    #pragma unroll
    for (int j = 0; j < 8; j++) {
        int c = nh * 64 + j * 8 + 2 * q;
        ps0 += acc1[j][0] * sA1[c] + acc1[j][1] * sA1[c + 1];
        pd0 += acc1[j][0] * sA1[128 + c] + acc1[j][1] * sA1[128 + c + 1];
        ps1 += acc1[j][2] * sA1[c] + acc1[j][3] * sA1[c + 1];
        pd1 += acc1[j][2] * sA1[128 + c] + acc1[j][3] * sA1[128 + c + 1];
        hrA[c >> 1] = __floats2half2_rn(acc1[j][0], acc1[j][1]);
        hrB[c >> 1] = __floats2half2_rn(acc1[j][2], acc1[j][3]);
    }
    float* h2aA = g_h2a + sbA * 64;
    float* h2aB = g_h2a + sbB * 64;
    #pragma unroll
    for (int j = 0; j < 4; j++) {
        int c = nh * 32 + j * 8 + 2 * q;
        *reinterpret_cast<float2*>(h2aA + c) = make_float2(acc2[j][0], acc2[j][1]);
        *reinterpret_cast<float2*>(h2aB + c) = make_float2(acc2[j][2], acc2[j][3]);
    }
    #pragma unroll
    for (int o = 1; o <= 2; o <<= 1) {
        ps0 += __shfl_xor_sync(0xffffffffu, ps0, o);
        pd0 += __shfl_xor_sync(0xffffffffu, pd0, o);
        ps1 += __shfl_xor_sync(0xffffffffu, ps1, o);
        pd1 += __shfl_xor_sync(0xffffffffu, pd1, o);
    }
    if (q == 0) {
        sr1[(nh * 64 + rowA) * 2 + 0] = ps0;
        sr1[(nh * 64 + rowA) * 2 + 1] = pd0;
        sr1[(nh * 64 + rowB) * 2 + 0] = ps1;
        sr1[(nh * 64 + rowB) * 2 + 1] = pd1;
    }
    __syncthreads();
    if (tid < 64) {
        size_t sb = (size_t)b * NN + row0 + tid;
        g_s1s[sb] = sr1[tid * 2]     + sr1[(64 + tid) * 2];
        g_s1d[sb] = sr1[tid * 2 + 1] + sr1[(64 + tid) * 2 + 1];
    }
}

// ---------------- K3: h2 = (r*state)@W2[64:] + h2a; full s2 scores ----------------
__global__ __launch_bounds__(256)
void k_h2b(const float* __restrict__ W2, const float* __restrict__ a2) {
    constexpr int AP = 72;
    constexpr int BP = 72;

    extern __shared__ char sm[];
    __half* As = (__half*)sm;                                // [64][AP]
    __half* Bs = (__half*)(sm + 64 * AP * 2);                // [64][BP]
    float*  sA = (float*)(sm + 64 * AP * 2 + 64 * BP * 2);   // [128]
    float*  sr = sA + 128;                                   // [256]

    int tid = threadIdx.x, w = tid >> 5, lane = tid & 31;
    int b = blockIdx.y;
    int row0 = blockIdx.x * 64;

    // ---- stage A = r*state: 64 rows x 64 ----
    #pragma unroll
    for (int it = 0; it < 2; it++) {
        int idx = it * 256 + tid;
        int row = idx >> 3;
        int col0 = (idx & 7) * 8;
        const float* src = g_rs + ((size_t)b * NN + row0 + row) * 64 + col0;
        float4 f0 = *reinterpret_cast<const float4*>(src);
        float4 f1 = *reinterpret_cast<const float4*>(src + 4);
        cvt_store8(As + row * AP + col0, f0, f1);
    }
    // ---- stage B = W2[64:128]: [64][64] ----
    #pragma unroll
    for (int it = 0; it < 2; it++) {
        int idx = it * 256 + tid;
        int k = idx >> 3;
        int n0 = (idx & 7) * 8;
        float4 f0 = *reinterpret_cast<const float4*>(W2 + (size_t)(64 + k) * 64 + n0);
        float4 f1 = *reinterpret_cast<const float4*>(W2 + (size_t)(64 + k) * 64 + n0 + 4);
        cvt_store8(Bs + k * BP + n0, f0, f1);
    }
    if (tid < 128) sA[tid] = a2[tid];
    __syncthreads();

    int mrow = (w & 3) * 16, nh = w >> 2;
    float acc[4][4];
    #pragma unroll
    for (int j = 0; j < 4; j++)
        #pragma unroll
        for (int q = 0; q < 4; q++) acc[j][q] = 0.f;

    uint32_t a_base = smem_u32(As + (mrow + (lane & 15)) * AP + ((lane >> 4) * 8));
    uint32_t b_base = smem_u32(Bs + (lane & 15) * BP + nh * 32 + ((lane >> 4) * 8));

    #pragma unroll
    for (int kk = 0; kk < 4; kk++) {
        uint32_t a0, a1, a2r, a3;
        ldm_x4(a0, a1, a2r, a3, a_base + kk * 32);
        #pragma unroll
        for (int j = 0; j < 2; j++) {
            uint32_t b0, b1, b2, b3;
            ldm_x4t(b0, b1, b2, b3, b_base + kk * (16 * BP * 2) + j * 32);
            mma16816(acc[2 * j],     a0, a1, a2r, a3, b0, b1);
            mma16816(acc[2 * j + 1], a0, a1, a2r, a3, b2, b3);
        }
    }

    // ---- epilogue: v = acc + h2a (full h2); store fp16; FULL s2 scores ----
    int q = lane & 3, g = lane >> 2;
    int rowA = mrow + g, rowB = rowA + 8;
    size_t sbA = (size_t)b * NN + row0 + rowA;
    size_t sbB = (size_t)b * NN + row0 + rowB;
    __half2* hrA = g_h2h + sbA * 32;
    __half2* hrB = g_h2h + sbB * 32;
    const float* h2aA = g_h2a + sbA * 64;
    const float* h2aB = g_h2a + sbB * 64;

    float ps0 = 0.f, pd0 = 0.f, ps1 = 0.f, pd1 = 0.f;
    #pragma unroll
    for (int j = 0; j < 4; j++) {
        int c = nh * 32 + j * 8 + 2 * q;
        float2 pa = *reinterpret_cast<const float2*>(h2aA + c);
        float2 pb = *reinterpret_cast<const float2*>(h2aB + c);
        float v0 = acc[j][0] + pa.x, v1 = acc[j][1] + pa.y;
        float v2 = acc[j][2] + pb.x, v3 = acc[j][3] + pb.y;
        ps0 += v0 * sA[c] + v1 * sA[c + 1];
        pd0 += v0 * sA[64 + c] + v1 * sA[64 + c + 1];
        ps1 += v2 * sA[c] + v3 * sA[c + 1];
        pd1 += v2 * sA[64 + c] + v3 * sA[64 + c + 1];
        hrA[c >> 1] = __floats2half2_rn(v0, v1);
        hrB[c >> 1] = __floats2half2_rn(v2, v3);
    }
    #pragma unroll
    for (int o = 1; o <= 2; o <<= 1) {
        ps0 += __shfl_xor_sync(0xffffffffu, ps0, o);
        pd0 += __shfl_xor_sync(0xffffffffu, pd0, o);
        ps1 += __shfl_xor_sync(0xffffffffu, ps1, o);
        pd1 += __shfl_xor_sync(0xffffffffu, pd1, o);
    }
    if (q == 0) {
        sr[(nh * 64 + rowA) * 2 + 0] = ps0;
        sr[(nh * 64 + rowA) * 2 + 1] = pd0;
        sr[(nh * 64 + rowB) * 2 + 0] = ps1;
        sr[(nh * 64 + rowB) * 2 + 1] = pd1;
    }
    __syncthreads();
    if (tid < 64) {
        size_t sb = (size_t)b * NN + row0 + tid;
        g_s2s[sb] = sr[tid * 2]     + sr[(64 + tid) * 2];   // '=' : full score, no double count
        g_s2d[sb] = sr[tid * 2 + 1] + sr[(64 + tid) * 2 + 1];
    }
}

// ---------------- K2: layer-1 attention + sigmoid gate (warp per (b,i)) ----
__global__ __launch_bounds__(128) void k_att1(const float* __restrict__ state) {
    int w = threadIdx.x >> 5, lane = threadIdx.x & 31;
    int i = blockIdx.x * 4 + w, b = blockIdx.y;
    int deg = g_cnt[i];
    float si = g_s1s[b * NN + i];

    float ek[4]; int nk[4];
    #pragma unroll
    for (int q = 0; q < 4; q++) {
        int k = q * 32 + lane;
        bool val = k < deg;
        int j = val ? g_nbr[i * MAXDEG + k] : 0;
        nk[q] = j;
        float e = val ? si + g_s1d[b * NN + j] : -3e38f;
        ek[q] = e > 0.f ? e : ALPHA * e;
    }
    float m = fmaxf(fmaxf(ek[0], ek[1]), fmaxf(ek[2], ek[3]));
    #pragma unroll
    for (int o = 16; o; o >>= 1) m = fmaxf(m, __shfl_xor_sync(0xffffffffu, m, o));
    float s = 0.f;
    #pragma unroll
    for (int q = 0; q < 4; q++) {
        ek[q] = (q * 32 + lane < deg) ? __expf(ek[q] - m) : 0.f;
        s += ek[q];
    }
    #pragma unroll
    for (int o = 16; o; o >>= 1) s += __shfl_xor_sync(0xffffffffu, s, o);
    float inv = 1.f / s;

    int hf = lane >> 4, cl = lane & 15;
    float acc[8];
    #pragma unroll
    for (int u = 0; u < 8; u++) acc[u] = 0.f;
    const __half2* hb = g_h1h + (size_t)b * NN * 64;
    #pragma unroll
    for (int q = 0; q < 4; q++) {
        if (q * 32 >= deg) break;
        int steps = deg - q * 32; if (steps > 32) steps = 32;
        int np = (steps + 1) >> 1;
        #pragma unroll 4
        for (int t = 0; t < np; t++) {
            int kl = 2 * t + hf;
            float wgt = __shfl_sync(0xffffffffu, ek[q], kl);
            int   j   = __shfl_sync(0xffffffffu, nk[q], kl);
            uint4 raw = *reinterpret_cast<const uint4*>(hb + (size_t)j * 64 + cl * 4);
            float2 f0 = __half22float2(*reinterpret_cast<__half2*>(&raw.x));
            float2 f1 = __half22float2(*reinterpret_cast<__half2*>(&raw.y));
            float2 f2 = __half22float2(*reinterpret_cast<__half2*>(&raw.z));
            float2 f3 = __half22float2(*reinterpret_cast<__half2*>(&raw.w));
            acc[0] += wgt * f0.x; acc[1] += wgt * f0.y;
            acc[2] += wgt * f1.x; acc[3] += wgt * f1.y;
            acc[4] += wgt * f2.x; acc[5] += wgt * f2.y;
            acc[6] += wgt * f3.x; acc[7] += wgt * f3.y;
        }
    }
    #pragma unroll
    for (int u = 0; u < 8; u++) acc[u] += __shfl_xor_sync(0xffffffffu, acc[u], 16);

    if (hf == 0) {
        float gv[8];
        #pragma unroll
        for (int u = 0; u < 8; u++) gv[u] = 1.f / (1.f + __expf(-acc[u] * inv));
        int idx = (b * NN + i) * 64;
        if (cl < 8) {
            int c0 = 8 * cl;
            float4 st0 = *reinterpret_cast<const float4*>(state + idx + c0);
            float4 st1 = *reinterpret_cast<const float4*>(state + idx + c0 + 4);
            float4 o0 = {gv[0] * st0.x, gv[1] * st0.y, gv[2] * st0.z, gv[3] * st0.w};
            float4 o1 = {gv[4] * st1.x, gv[5] * st1.y, gv[6] * st1.z, gv[7] * st1.w};
            *reinterpret_cast<float4*>(g_rs + idx + c0)     = o0;
            *reinterpret_cast<float4*>(g_rs + idx + c0 + 4) = o1;
        } else {
            int c0 = 8 * cl - 64;
            float4 o0 = {gv[0], gv[1], gv[2], gv[3]};
            float4 o1 = {gv[4], gv[5], gv[6], gv[7]};
            *reinterpret_cast<float4*>(g_z + idx + c0)     = o0;
            *reinterpret_cast<float4*>(g_z + idx + c0 + 4) = o1;
        }
    }
}

// ---------------- K4: layer-2 attention + tanh + GRU blend ----------------
__global__ __launch_bounds__(128) void k_att2(const float* __restrict__ state,
                                              float* __restrict__ out) {
    int w = threadIdx.x >> 5, lane = threadIdx.x & 31;
    int i = blockIdx.x * 4 + w, b = blockIdx.y;
    int deg = g_cnt[i];
    float si = g_s2s[b * NN + i];

    float ek[4]; int nk[4];
    #pragma unroll
    for (int q = 0; q < 4; q++) {
        int k = q * 32 + lane;
        bool val = k < deg;
        int j = val ? g_nbr[i * MAXDEG + k] : 0;
        nk[q] = j;
        float e = val ? si + g_s2d[b * NN + j] : -3e38f;
        ek[q] = e > 0.f ? e : ALPHA * e;
    }
    float m = fmaxf(fmaxf(ek[0], ek[1]), fmaxf(ek[2], ek[3]));
    #pragma unroll
    for (int o = 16; o; o >>= 1) m = fmaxf(m, __shfl_xor_sync(0xffffffffu, m, o));
    float s = 0.f;
    #pragma unroll
    for (int q = 0; q < 4; q++) {
        ek[q] = (q * 32 + lane < deg) ? __expf(ek[q] - m) : 0.f;
        s += ek[q];
    }
    #pragma unroll
    for (int o = 16; o; o >>= 1) s += __shfl_xor_sync(0xffffffffu, s, o);
    float inv = 1.f / s;

    int hf = lane >> 3, cl = lane & 7;
    float acc[8];
    #pragma unroll
    for (int u = 0; u < 8; u++) acc[u] = 0.f;
    const __half2* hb = g_h2h + (size_t)b * NN * 32;
    #pragma unroll
    for (int q = 0; q < 4; q++) {
        if (q * 32 >= deg) break;
        int steps = deg - q * 32; if (steps > 32) steps = 32;
        int np = (steps + 3) >> 2;
        #pragma unroll 4
        for (int t = 0; t < np; t++) {
            int kl = 4 * t + hf;
            float wgt = __shfl_sync(0xffffffffu, ek[q], kl);
            int   j   = __shfl_sync(0xffffffffu, nk[q], kl);
            uint4 raw = *reinterpret_cast<const uint4*>(hb + (size_t)j * 32 + cl * 4);
            float2 f0 = __half22float2(*reinterpret_cast<__half2*>(&raw.x));
            float2 f1 = __half22float2(*reinterpret_cast<__half2*>(&raw.y));
            float2 f2 = __half22float2(*reinterpret_cast<__half2*>(&raw.z));
            float2 f3 = __half22float2(*reinterpret_cast<__half2*>(&raw.w));
            acc[0] += wgt * f0.x; acc[1] += wgt * f0.y;
            acc[2] += wgt * f1.x; acc[3] += wgt * f1.y;
            acc[4] += wgt * f2.x; acc[5] += wgt * f2.y;
            acc[6] += wgt * f3.x; acc[7] += wgt * f3.y;
        }
    }
    #pragma unroll
    for (int u = 0; u < 8; u++) {
        acc[u] += __shfl_xor_sync(0xffffffffu, acc[u], 8);
        acc[u] += __shfl_xor_sync(0xffffffffu, acc[u], 16);
    }

    if (lane < 8) {
        int idx = (b * NN + i) * 64 + 8 * cl;
        float4 z0 = *reinterpret_cast<const float4*>(g_z + idx);
        float4 z1 = *reinterpret_cast<const float4*>(g_z + idx + 4);
        float4 s0 = *reinterpret_cast<const float4*>(state + idx);
        float4 s1 = *reinterpret_cast<const float4*>(state + idx + 4);
        float4 o0, o1;
        o0.x = z0.x * s0.x + (1.f - z0.x) * tanhf(acc[0] * inv);
        o0.y = z0.y * s0.y + (1.f - z0.y) * tanhf(acc[1] * inv);
        o0.z = z0.z * s0.z + (1.f - z0.z) * tanhf(acc[2] * inv);
        o0.w = z0.w * s0.w + (1.f - z0.w) * tanhf(acc[3] * inv);
        o1.x = z1.x * s1.x + (1.f - z1.x) * tanhf(acc[4] * inv);
        o1.y = z1.y * s1.y + (1.f - z1.y) * tanhf(acc[5] * inv);
        o1.z = z1.z * s1.z + (1.f - z1.z) * tanhf(acc[6] * inv);
        o1.w = z1.w * s1.w + (1.f - z1.w) * tanhf(acc[7] * inv);
        *reinterpret_cast<float4*>(out + idx)     = o0;
        *reinterpret_cast<float4*>(out + idx + 4) = o1;
    }
}

// ---------------- launch ----------------
extern "C" void kernel_launch(void* const* d_in, const int* in_sizes, int n_in,
                              void* d_out, int out_size) {
    const float* X     = (const float*)d_in[0];
    const float* state = (const float*)d_in[1];
    const float* adj   = (const float*)d_in[2];
    const float* W1    = (const float*)d_in[3];
    const float* a1    = (const float*)d_in[4];
    const float* W2    = (const float*)d_in[5];
    const float* a2    = (const float*)d_in[6];
    float* out = (float*)d_out;

    const int SMEM_G1  = 64 * 136 * 2 + 128 * 136 * 2 + 64 * 72 * 2 +
                         (256 + 256) * 4;                             // ~63 KB
    const int SMEM_H2B = 64 * 72 * 2 + 64 * 72 * 2 + (128 + 256) * 4; // ~20 KB

    static int inited = 0;
    static cudaStream_t s_side = 0;
    static cudaEvent_t ev_fork = 0, ev_join = 0;
    if (!inited) {
        cudaFuncSetAttribute(k_g1,  cudaFuncAttributeMaxDynamicSharedMemorySize, SMEM_G1);
        cudaFuncSetAttribute(k_h2b, cudaFuncAttributeMaxDynamicSharedMemorySize, SMEM_H2B);
        cudaStreamCreateWithFlags(&s_side, cudaStreamNonBlocking);
        cudaEventCreateWithFlags(&ev_fork, cudaEventDisableTiming);
        cudaEventCreateWithFlags(&ev_join, cudaEventDisableTiming);
        inited = 1;
    }

    dim3 gt(NN / 64, BB);           // 16 x 16 = 256 blocks
    dim3 ga(NN / 4, BB);            // warp per (b,i)

    if (s_side) {
        cudaEventRecord(ev_fork, 0);
        cudaStreamWaitEvent(s_side, ev_fork, 0);
        k_build<<<NN, 256, 0, s_side>>>(adj);
        cudaEventRecord(ev_join, s_side);

        k_g1<<<gt, 256, SMEM_G1>>>(X, state, W1, a1, W2);
        cudaStreamWaitEvent(0, ev_join, 0);
    } else {
        k_build<<<NN, 256>>>(adj);
        k_g1<<<gt, 256, SMEM_G1>>>(X, state, W1, a1, W2);
    }

    k_att1<<<ga, 128>>>(state);
    k_h2b<<<gt, 256, SMEM_H2B>>>(W2, a2);
    k_att2<<<ga, 128>>>(state, out);
}